// round 10
// baseline (speedup 1.0000x reference)
#include <cuda_runtime.h>

#define NG 1024
#define NN 40
#define M_EDGES 780
#define NODES (NG*NN)          /* 40960 */
#define H_ELEMS (NODES*64)     /* 2621440 */
#define X_PER_G (160*160)      /* 25600 */
#define X_ELEMS ((size_t)NG*X_PER_G)

// scratch: u = hg @ We0 per node (10.5 MB, L2-resident)
__device__ float g_u[NODES * 64];
// fallback scratch if the harness's d_out does not cover h and/or X
__device__ float g_h[H_ELEMS];
__device__ float g_x[NG * X_PER_G];

__constant__ int c_smat[16] = {0,1,2,3, 1,4,5,6, 2,5,7,8, 3,6,8,9};

__device__ __forceinline__ float lrelu(float v){ return v > 0.f ? v : 0.1f*v; }

typedef unsigned long long ull;

// packed fp32x2 FMA (sm_10x): 2 MACs per instruction, fp32-peak path
__device__ __forceinline__ ull ffma2(ull a, ull b, ull c){
    ull d;
    asm("fma.rn.f32x2 %0, %1, %2, %3;" : "=l"(d) : "l"(a), "l"(b), "l"(c));
    return d;
}
__device__ __forceinline__ ull splat2(float x){
    ull r;
    asm("mov.b64 %0, {%1, %1};" : "=l"(r) : "f"(x));
    return r;
}
__device__ __forceinline__ float f2lo(ull a){ return __uint_as_float((unsigned)(a & 0xffffffffULL)); }
__device__ __forceinline__ float f2hi(ull a){ return __uint_as_float((unsigned)(a >> 32)); }

// no-op kernel: with ONE dummy, edge_kernel sits in the ncu capture slot (#4)
__global__ void dummy_kernel(){}

// ---------------------------------------------------------------------------
// K1: GCN — complete graph => gcn(h)[j] = (colsum(t) - t[j])/39 + b, t = h@W
// ---------------------------------------------------------------------------
__global__ __launch_bounds__(128) void gcn_kernel(
    const float* __restrict__ x,
    const float* __restrict__ Wg0, const float* __restrict__ bg0,
    const float* __restrict__ Wg1, const float* __restrict__ bg1,
    const float* __restrict__ Wg2, const float* __restrict__ bg2,
    float* __restrict__ hout)
{
    __shared__ float sh[NN*64];      // activations [n][k] stride 64
    __shared__ float st[NN*64];      // t = h@W     [n][o] stride 64
    __shared__ float swt[64*36];     // W^T [o][k] stride 36 (pad: conflict-free)
    __shared__ float ssum[64];
    const int g = blockIdx.x, tid = threadIdx.x;

    for (int idx = tid; idx < NN*64; idx += 128) sh[idx] = 0.f;
    __syncthreads();
    for (int idx = tid; idx < NN*6; idx += 128){
        int n = idx/6, c = idx - n*6;
        sh[n*64+c] = x[(g*NN+n)*16 + c];
    }
    __syncthreads();

    auto finish = [&](int outd, const float* b, bool act){
        for (int o = tid; o < outd; o += 128){
            float s = 0.f;
            for (int n = 0; n < NN; n++) s += st[n*64+o];
            ssum[o] = s;
        }
        __syncthreads();
        const float inv = 1.f/39.f;
        for (int idx = tid; idx < NN*outd; idx += 128){
            int n = idx/outd, o = idx - n*outd;
            float v = (ssum[o] - st[n*64+o])*inv + b[o];
            if (act) v = lrelu(v);
            sh[n*64+o] = v;
        }
        __syncthreads();
    };

    // layer 0: ind=6 (scalar, tiny)
    {
        for (int idx = tid; idx < 6*32; idx += 128) swt[idx] = Wg0[idx]; // [k][o]
        __syncthreads();
        for (int idx = tid; idx < NN*32; idx += 128){
            int n = idx/32, o = idx & 31;
            float a = 0.f;
#pragma unroll
            for (int k = 0; k < 6; k++) a += sh[n*64+k]*swt[k*32+o];
            st[n*64+o] = a;
        }
        __syncthreads();
        finish(32, bg0, true);
    }

    auto layerV = [&](const float* W, const float* b, int outd, bool act){
        for (int idx = tid; idx < 32*outd; idx += 128){
            int k = idx / outd, o = idx - k*outd;
            swt[o*36 + k] = W[idx];
        }
        __syncthreads();
        for (int idx = tid; idx < NN*outd; idx += 128){
            int n = idx/outd, o = idx - n*outd;
            const float4* A = reinterpret_cast<const float4*>(sh + n*64);
            const float4* B = reinterpret_cast<const float4*>(swt + o*36);
            float ax=0.f, ay=0.f, az=0.f, aw=0.f;
#pragma unroll
            for (int q = 0; q < 8; q++){
                float4 a = A[q], w = B[q];
                ax += a.x*w.x; ay += a.y*w.y; az += a.z*w.z; aw += a.w*w.w;
            }
            st[n*64+o] = (ax+ay)+(az+aw);
        }
        __syncthreads();
        finish(outd, b, act);
    };
    layerV(Wg1, bg1, 32, true);
    layerV(Wg2, bg2, 64, false);

    float* hrow = hout + (size_t)g*NN*64;
    for (int idx = tid; idx < NN*64; idx += 128) hrow[idx] = sh[idx];
}

// ---------------------------------------------------------------------------
// 128x64x64 GEMM mainloop, 512 threads, thread tile = 2 rows x 8 outs.
// eg = tid&63 (2 rows each), og = tid>>6 (8 outs each).
// Zin: [k][e] stride 128. Wsm: [k][o] plain 64x64 (warp-uniform loads).
// acc[e*4+op] = f32x2 over outputs (og*8+2*op, og*8+2*op+1), edge eg*2+e.
// ---------------------------------------------------------------------------
__device__ __forceinline__ void gemm_main(const float* Zin, const float* Wsm,
                                          int eg, int og, ull* acc)
{
#pragma unroll
    for (int i = 0; i < 8; i++) acc[i] = 0ULL;
#pragma unroll 4
    for (int k = 0; k < 64; k++){
        float2 z = *reinterpret_cast<const float2*>(Zin + k*128 + eg*2);
        ulonglong2 wA = *reinterpret_cast<const ulonglong2*>(Wsm + k*64 + og*8);
        ulonglong2 wB = *reinterpret_cast<const ulonglong2*>(Wsm + k*64 + og*8 + 4);
        ull z0 = splat2(z.x), z1 = splat2(z.y);
        acc[0] = ffma2(z0, wA.x, acc[0]);  acc[1] = ffma2(z0, wA.y, acc[1]);
        acc[2] = ffma2(z0, wB.x, acc[2]);  acc[3] = ffma2(z0, wB.y, acc[3]);
        acc[4] = ffma2(z1, wA.x, acc[4]);  acc[5] = ffma2(z1, wA.y, acc[5]);
        acc[6] = ffma2(z1, wB.x, acc[6]);  acc[7] = ffma2(z1, wB.y, acc[7]);
    }
}

// smem epilogue: Zout[o][e] stride 128; barrier before writes (in-place safe).
// Adjacent edges (eg*2, eg*2+1) pack into float2 stores.
template<bool ACT>
__device__ __forceinline__ void gemm_store_smem(float* Zout, const float* bias,
                                                int eg, int og, ull* acc)
{
    float b[8];
#pragma unroll
    for (int q = 0; q < 8; q++) b[q] = bias[og*8+q];
    __syncthreads();
#pragma unroll
    for (int op = 0; op < 4; op++){
        ull A0 = acc[op], A1 = acc[4+op];
        float lo0 = f2lo(A0) + b[2*op],   hi0 = f2hi(A0) + b[2*op+1];
        float lo1 = f2lo(A1) + b[2*op],   hi1 = f2hi(A1) + b[2*op+1];
        if (ACT){ lo0=lrelu(lo0); hi0=lrelu(hi0); lo1=lrelu(lo1); hi1=lrelu(hi1); }
        *reinterpret_cast<float2*>(Zout + (og*8+2*op)*128   + eg*2) = make_float2(lo0, lo1);
        *reinterpret_cast<float2*>(Zout + (og*8+2*op+1)*128 + eg*2) = make_float2(hi0, hi1);
    }
}

// global epilogue: stream accumulators straight to g_u rows (no bias/act)
__device__ __forceinline__ void gemm_store_gu(float* gu, int r0,
                                              int eg, int og, ull* acc)
{
#pragma unroll
    for (int e = 0; e < 2; e++){
        int row = r0 + eg*2 + e;
        float4 v0 = make_float4(f2lo(acc[e*4+0]), f2hi(acc[e*4+0]),
                                f2lo(acc[e*4+1]), f2hi(acc[e*4+1]));
        float4 v1 = make_float4(f2lo(acc[e*4+2]), f2hi(acc[e*4+2]),
                                f2lo(acc[e*4+3]), f2hi(acc[e*4+3]));
        *reinterpret_cast<float4*>(gu + (size_t)row*64 + og*8)     = v0;
        *reinterpret_cast<float4*>(gu + (size_t)row*64 + og*8 + 4) = v1;
    }
}

// Final 64->10 layer, 512 threads: e = tid&127, q = tid>>7 (k-quarter).
__device__ __forceinline__ void layer10(const float* Zin, const float* wsh,
                                        float* part, int e, int q)
{
    ull acc[5];
#pragma unroll
    for (int p = 0; p < 5; p++) acc[p] = 0ULL;
    const int k0 = q*16;
#pragma unroll 4
    for (int kk = 0; kk < 16; kk++){
        int k = k0 + kk;
        ull z2 = splat2(Zin[k*128+e]);
        const float* wr = wsh + k*10;
#pragma unroll
        for (int p = 0; p < 5; p++){
            ull w = *reinterpret_cast<const ull*>(wr + p*2);
            acc[p] = ffma2(z2, w, acc[p]);
        }
    }
    float* pr = part + q*1280 + e*10;
#pragma unroll
    for (int p = 0; p < 5; p++){ pr[p*2] = f2lo(acc[p]); pr[p*2+1] = f2hi(acc[p]); }
}

// ---------------------------------------------------------------------------
// K2: per-node — u = hg@We0 (streamed to g_u), vp = MLP(hg) -> diag blocks.
// 128 nodes per block, 512 threads, grid 320. smem ~72.5KB -> 2 blocks/SM.
// ---------------------------------------------------------------------------
#define K2_SMEM_FLOATS 18128
__global__ __launch_bounds__(512, 2) void node_kernel(
    const float* __restrict__ hg,
    const float* __restrict__ Wn0, const float* __restrict__ bn0,
    const float* __restrict__ Wn1, const float* __restrict__ bn1,
    const float* __restrict__ Wn2, const float* __restrict__ bn2,
    const float* __restrict__ We0,
    float* __restrict__ Xout)
{
    extern __shared__ float sm[];
    float* Z0   = sm;             // 8192
    float* Wsm  = sm + 8192;      // 4096
    float* wsh  = sm + 12288;     // 640
    float* part = sm + 12928;     // 5120 (4 k-quarters x 128 x 10)
    float* bsh  = sm + 18048;     // 64
    float* b2   = sm + 18112;     // 16

    const int tid = threadIdx.x;
    const int e  = tid & 127, q = tid >> 7;
    const int eg = tid & 63,  og = tid >> 6;
    const int r0 = blockIdx.x * 128;
    ull acc[8];

    // transpose-load: Z0[k][e] = hg[r0+e][k] (each thread: 16 k of one row)
    {
        const float4* row = reinterpret_cast<const float4*>(hg + (size_t)(r0+e)*64);
#pragma unroll
        for (int t = 0; t < 4; t++){
            float4 v = row[q*4+t];
            int k = q*16 + t*4;
            Z0[(k+0)*128+e]=v.x; Z0[(k+1)*128+e]=v.y; Z0[(k+2)*128+e]=v.z; Z0[(k+3)*128+e]=v.w;
        }
    }
    for (int i2 = tid; i2 < 4096; i2 += 512) Wsm[i2] = We0[i2];
    __syncthreads();
    gemm_main(Z0, Wsm, eg, og, acc);            // u = hg @ We0
    gemm_store_gu(g_u, r0, eg, og, acc);        // straight to global
    __syncthreads();
    for (int i2 = tid; i2 < 4096; i2 += 512) Wsm[i2] = Wn0[i2];
    for (int i2 = tid; i2 < 64; i2 += 512) bsh[i2] = bn0[i2];
    __syncthreads();
    gemm_main(Z0, Wsm, eg, og, acc);
    gemm_store_smem<true>(Z0, bsh, eg, og, acc);   // in-place (barrier inside)
    __syncthreads();
    for (int i2 = tid; i2 < 4096; i2 += 512) Wsm[i2] = Wn1[i2];
    for (int i2 = tid; i2 < 64; i2 += 512) bsh[i2] = bn1[i2];
    __syncthreads();
    gemm_main(Z0, Wsm, eg, og, acc);
    gemm_store_smem<true>(Z0, bsh, eg, og, acc);   // in-place
    __syncthreads();
    for (int i2 = tid; i2 < 640; i2 += 512) wsh[i2] = Wn2[i2];
    if (tid < 10) b2[tid] = bn2[tid];
    __syncthreads();
    layer10(Z0, wsh, part, e, q);
    __syncthreads();

    // diagonal 4x4 blocks: 128 nodes x 4 rows = 512 stores, one per thread
    {
        int n = tid >> 2, a = tid & 3;
        int r = r0 + n, gg = r/40, i = r - gg*40;
        const float* p0 = part + n*10;
        const float* p1 = part + 1280 + n*10;
        const float* p2 = part + 2560 + n*10;
        const float* p3 = part + 3840 + n*10;
        int s0=c_smat[a*4], s1=c_smat[a*4+1], s2=c_smat[a*4+2], s3=c_smat[a*4+3];
        float4 v = make_float4(p0[s0]+p1[s0]+p2[s0]+p3[s0]+b2[s0],
                               p0[s1]+p1[s1]+p2[s1]+p3[s1]+b2[s1],
                               p0[s2]+p1[s2]+p2[s2]+p3[s2]+b2[s2],
                               p0[s3]+p1[s3]+p2[s3]+p3[s3]+b2[s3]);
        *reinterpret_cast<float4*>(Xout + (size_t)gg*X_PER_G + (i*4+a)*160 + i*4) = v;
    }
}

// ---------------------------------------------------------------------------
// K3: per-edge — 2 blocks per group (grid 2048, 512 threads), ~85KB smem ->
// 2 blocks/SM (32 warps). Tiles of 128 edges interleaved between halves.
//   z1 = lrelu(u_i+u_j+be0); z2 = lrelu(z1@We1+be1) IN-PLACE; ep = z2@We2+be2;
//   write symmetric 4x4 blocks to X at (i,j) and (j,i).
// ---------------------------------------------------------------------------
#define K3_SMEM_FLOATS 21168
__global__ __launch_bounds__(512, 2) void edge_kernel(
    const int* __restrict__ ud,   /* int32 pairs (i,j) */
    const float* __restrict__ be0,
    const float* __restrict__ We1, const float* __restrict__ be1,
    const float* __restrict__ We2, const float* __restrict__ be2,
    float* __restrict__ Xout)
{
    extern __shared__ float sm[];
    float* ug   = sm;              // 40*68 = 2720 (16B-aligned rows)
    float* Z0   = sm + 2720;       // 8192
    float* Wsm  = sm + 10912;      // 4096
    float* wsh  = sm + 15008;      // 640
    float* part = sm + 15648;      // 5120
    float* b0   = sm + 20768;      // 64
    float* b1   = sm + 20832;      // 64
    float* b2   = sm + 20896;      // 16
    int*   si   = (int*)(sm + 20912); // 128
    int*   sj   = (int*)(sm + 21040); // 128

    const int tid = threadIdx.x;
    const int e  = tid & 127, q = tid >> 7;
    const int eg = tid & 63,  og = tid >> 6;
    const int g    = blockIdx.x >> 1;
    const int half = blockIdx.x & 1;
    ull acc[8];

    {   // group's u rows into shared, stride 68, float4 both sides
        const float4* usrc = reinterpret_cast<const float4*>(g_u + (size_t)g*NN*64);
        for (int idx = tid; idx < NN*16; idx += 512){
            int n = idx >> 4, c4 = idx & 15;
            *reinterpret_cast<float4*>(ug + n*68 + c4*4) = usrc[idx];
        }
    }
    for (int i2 = tid; i2 < 4096; i2 += 512) Wsm[i2] = We1[i2];
    for (int i2 = tid; i2 < 64; i2 += 512){ b0[i2] = be0[i2]; b1[i2] = be1[i2]; }
    for (int i2 = tid; i2 < 640; i2 += 512) wsh[i2] = We2[i2];
    if (tid < 10) b2[tid] = be2[tid];

    float* Xg = Xout + (size_t)g*X_PER_G;

    for (int tile = half; tile < 7; tile += 2){
        const int m0 = tile*128;
        const int ecnt = min(128, M_EDGES - m0);

        __syncthreads();   // prev scatter done reading si/sj; setup visible (1st iter)
        if (tid < 128){
            int2 p = make_int2(0,0);
            if (tid < ecnt) p = *reinterpret_cast<const int2*>(ud + 2*(m0+tid));
            si[tid] = p.x; sj[tid] = p.y;
        }
        __syncthreads();

        {   // z1 -> Z0: 4 threads per edge, 16 k each, vectorized reads
            const bool valid = e < ecnt;
            const int i = si[e], j = sj[e];
            const float4* ui = reinterpret_cast<const float4*>(ug + i*68 + q*16);
            const float4* uj = reinterpret_cast<const float4*>(ug + j*68 + q*16);
            const float4* bb = reinterpret_cast<const float4*>(b0 + q*16);
#pragma unroll
            for (int t = 0; t < 4; t++){
                float4 a = ui[t], b = uj[t], c = bb[t];
                float4 v;
                v.x = valid ? lrelu(a.x+b.x+c.x) : 0.f;
                v.y = valid ? lrelu(a.y+b.y+c.y) : 0.f;
                v.z = valid ? lrelu(a.z+b.z+c.z) : 0.f;
                v.w = valid ? lrelu(a.w+b.w+c.w) : 0.f;
                int k = q*16 + t*4;
                Z0[(k+0)*128+e]=v.x; Z0[(k+1)*128+e]=v.y;
                Z0[(k+2)*128+e]=v.z; Z0[(k+3)*128+e]=v.w;
            }
        }
        __syncthreads();
        gemm_main(Z0, Wsm, eg, og, acc);
        gemm_store_smem<true>(Z0, b1, eg, og, acc);   // in-place (barrier inside)
        __syncthreads();
        layer10(Z0, wsh, part, e, q);
        __syncthreads();

#pragma unroll
        for (int p = 0; p < 2; p++){
            int idx = tid + p*512;              // 0..1023
            int ee = idx >> 3, side = (idx >> 2) & 1, a = idx & 3;
            if (ee < ecnt){
                int i = si[ee], j = sj[ee];
                const float* p0 = part + ee*10;
                const float* p1 = part + 1280 + ee*10;
                const float* p2 = part + 2560 + ee*10;
                const float* p3 = part + 3840 + ee*10;
                int s0=c_smat[a*4], s1=c_smat[a*4+1], s2=c_smat[a*4+2], s3=c_smat[a*4+3];
                float4 v = make_float4(p0[s0]+p1[s0]+p2[s0]+p3[s0]+b2[s0],
                                       p0[s1]+p1[s1]+p2[s1]+p3[s1]+b2[s1],
                                       p0[s2]+p1[s2]+p2[s2]+p3[s2]+b2[s2],
                                       p0[s3]+p1[s3]+p2[s3]+p3[s3]+b2[s3]);
                int bi = side ? j : i;
                int bj = side ? i : j;
                *reinterpret_cast<float4*>(Xg + (bi*4+a)*160 + bj*4) = v;
            }
        }
    }
}

// ---------------------------------------------------------------------------
extern "C" void kernel_launch(void* const* d_in, const int* in_sizes, int n_in,
                              void* d_out, int out_size)
{
    const float* x  = (const float*)d_in[0];
    // d_in[1] edge_index (unused: complete graph), d_in[3] edge_map (unused)
    const int*   ud = (const int*)d_in[2];   // int32 (JAX default x64 disabled)
    const float* Wg0 = (const float*)d_in[4];  const float* bg0 = (const float*)d_in[5];
    const float* Wg1 = (const float*)d_in[6];  const float* bg1 = (const float*)d_in[7];
    const float* Wg2 = (const float*)d_in[8];  const float* bg2 = (const float*)d_in[9];
    const float* Wn0 = (const float*)d_in[10]; const float* bn0 = (const float*)d_in[11];
    const float* Wn1 = (const float*)d_in[12]; const float* bn1 = (const float*)d_in[13];
    const float* Wn2 = (const float*)d_in[14]; const float* bn2 = (const float*)d_in[15];
    const float* We0 = (const float*)d_in[16]; const float* be0 = (const float*)d_in[17];
    const float* We1 = (const float*)d_in[18]; const float* be1 = (const float*)d_in[19];
    const float* We2 = (const float*)d_in[20]; const float* be2 = (const float*)d_in[21];

    // Adaptive output layout: reference returns (h, X).
    float* hout;
    float* Xout;
    size_t osz = (size_t)out_size;
    if (osz >= (size_t)H_ELEMS + X_ELEMS){
        hout = (float*)d_out;
        Xout = (float*)d_out + H_ELEMS;
    } else if (osz >= X_ELEMS){
        cudaGetSymbolAddress((void**)&hout, g_h);
        Xout = (float*)d_out;
    } else {
        hout = (float*)d_out;
        cudaGetSymbolAddress((void**)&Xout, g_x);
    }

    cudaFuncSetAttribute(node_kernel, cudaFuncAttributeMaxDynamicSharedMemorySize,
                         K2_SMEM_FLOATS*4);
    cudaFuncSetAttribute(edge_kernel, cudaFuncAttributeMaxDynamicSharedMemorySize,
                         K3_SMEM_FLOATS*4);

    dummy_kernel<<<1, 32>>>();   // exactly one: puts edge_kernel in ncu slot #4
    gcn_kernel<<<NG, 128>>>(x, Wg0, bg0, Wg1, bg1, Wg2, bg2, hout);
    node_kernel<<<NODES/128, 512, K2_SMEM_FLOATS*4>>>(hout, Wn0, bn0, Wn1, bn1,
                                                      Wn2, bn2, We0, Xout);
    edge_kernel<<<NG*2, 512, K3_SMEM_FLOATS*4>>>(ud, be0, We1, be1,
                                                 We2, be2, Xout);
}

// round 16
// speedup vs baseline: 1.1342x; 1.1342x over previous
#include <cuda_runtime.h>

#define NG 1024
#define NN 40
#define M_EDGES 780
#define NODES (NG*NN)          /* 40960 */
#define H_ELEMS (NODES*64)     /* 2621440 */
#define X_PER_G (160*160)      /* 25600 */
#define X_ELEMS ((size_t)NG*X_PER_G)

// scratch: u = hg @ We0 per node (10.5 MB, L2-resident)
__device__ float g_u[NODES * 64];
// fallback scratch if the harness's d_out does not cover h and/or X
__device__ float g_h[H_ELEMS];
__device__ float g_x[NG * X_PER_G];

__constant__ int c_smat[16] = {0,1,2,3, 1,4,5,6, 2,5,7,8, 3,6,8,9};

__device__ __forceinline__ float lrelu(float v){ return v > 0.f ? v : 0.1f*v; }

typedef unsigned long long ull;

// packed fp32x2 FMA (sm_10x): 2 MACs per instruction
__device__ __forceinline__ ull ffma2(ull a, ull b, ull c){
    ull d;
    asm("fma.rn.f32x2 %0, %1, %2, %3;" : "=l"(d) : "l"(a), "l"(b), "l"(c));
    return d;
}
__device__ __forceinline__ ull splat2(float x){
    ull r;
    asm("mov.b64 %0, {%1, %1};" : "=l"(r) : "f"(x));
    return r;
}
__device__ __forceinline__ float f2lo(ull a){ return __uint_as_float((unsigned)(a & 0xffffffffULL)); }
__device__ __forceinline__ float f2hi(ull a){ return __uint_as_float((unsigned)(a >> 32)); }

// no-op kernel: ONE dummy puts edge_kernel in the ncu capture slot (#4)
__global__ void dummy_kernel(){}

// ---------------------------------------------------------------------------
// K1: GCN — complete graph => gcn(h)[j] = (colsum(t) - t[j])/39 + b, t = h@W
// ---------------------------------------------------------------------------
__global__ __launch_bounds__(128) void gcn_kernel(
    const float* __restrict__ x,
    const float* __restrict__ Wg0, const float* __restrict__ bg0,
    const float* __restrict__ Wg1, const float* __restrict__ bg1,
    const float* __restrict__ Wg2, const float* __restrict__ bg2,
    float* __restrict__ hout)
{
    __shared__ float sh[NN*64];
    __shared__ float st[NN*64];
    __shared__ float swt[64*36];
    __shared__ float ssum[64];
    const int g = blockIdx.x, tid = threadIdx.x;

    for (int idx = tid; idx < NN*64; idx += 128) sh[idx] = 0.f;
    __syncthreads();
    for (int idx = tid; idx < NN*6; idx += 128){
        int n = idx/6, c = idx - n*6;
        sh[n*64+c] = x[(g*NN+n)*16 + c];
    }
    __syncthreads();

    auto finish = [&](int outd, const float* b, bool act){
        for (int o = tid; o < outd; o += 128){
            float s = 0.f;
            for (int n = 0; n < NN; n++) s += st[n*64+o];
            ssum[o] = s;
        }
        __syncthreads();
        const float inv = 1.f/39.f;
        for (int idx = tid; idx < NN*outd; idx += 128){
            int n = idx/outd, o = idx - n*outd;
            float v = (ssum[o] - st[n*64+o])*inv + b[o];
            if (act) v = lrelu(v);
            sh[n*64+o] = v;
        }
        __syncthreads();
    };

    {
        for (int idx = tid; idx < 6*32; idx += 128) swt[idx] = Wg0[idx];
        __syncthreads();
        for (int idx = tid; idx < NN*32; idx += 128){
            int n = idx/32, o = idx & 31;
            float a = 0.f;
#pragma unroll
            for (int k = 0; k < 6; k++) a += sh[n*64+k]*swt[k*32+o];
            st[n*64+o] = a;
        }
        __syncthreads();
        finish(32, bg0, true);
    }

    auto layerV = [&](const float* W, const float* b, int outd, bool act){
        for (int idx = tid; idx < 32*outd; idx += 128){
            int k = idx / outd, o = idx - k*outd;
            swt[o*36 + k] = W[idx];
        }
        __syncthreads();
        for (int idx = tid; idx < NN*outd; idx += 128){
            int n = idx/outd, o = idx - n*outd;
            const float4* A = reinterpret_cast<const float4*>(sh + n*64);
            const float4* B = reinterpret_cast<const float4*>(swt + o*36);
            float ax=0.f, ay=0.f, az=0.f, aw=0.f;
#pragma unroll
            for (int q = 0; q < 8; q++){
                float4 a = A[q], w = B[q];
                ax += a.x*w.x; ay += a.y*w.y; az += a.z*w.z; aw += a.w*w.w;
            }
            st[n*64+o] = (ax+ay)+(az+aw);
        }
        __syncthreads();
        finish(outd, b, act);
    };
    layerV(Wg1, bg1, 32, true);
    layerV(Wg2, bg2, 64, false);

    float* hrow = hout + (size_t)g*NN*64;
    for (int idx = tid; idx < NN*64; idx += 128) hrow[idx] = sh[idx];
}

// ---------------------------------------------------------------------------
// SIMT 128x64x64 GEMM (r4c8, node kernel — R9 proven)
// ---------------------------------------------------------------------------
__device__ __forceinline__ void gemm_main(const float* Zin, const float* Wsm,
                                          int eg, int og, ull* acc)
{
#pragma unroll
    for (int i = 0; i < 16; i++) acc[i] = 0ULL;
#pragma unroll 4
    for (int k = 0; k < 64; k++){
        float4 z = *reinterpret_cast<const float4*>(Zin + k*128 + eg*4);
        ulonglong2 wA = *reinterpret_cast<const ulonglong2*>(Wsm + k*64 + og*8);
        ulonglong2 wB = *reinterpret_cast<const ulonglong2*>(Wsm + k*64 + og*8 + 4);
        ull z0 = splat2(z.x), z1 = splat2(z.y), z2 = splat2(z.z), z3 = splat2(z.w);
        acc[0] = ffma2(z0, wA.x, acc[0]);  acc[1]  = ffma2(z0, wA.y, acc[1]);
        acc[2] = ffma2(z0, wB.x, acc[2]);  acc[3]  = ffma2(z0, wB.y, acc[3]);
        acc[4] = ffma2(z1, wA.x, acc[4]);  acc[5]  = ffma2(z1, wA.y, acc[5]);
        acc[6] = ffma2(z1, wB.x, acc[6]);  acc[7]  = ffma2(z1, wB.y, acc[7]);
        acc[8] = ffma2(z2, wA.x, acc[8]);  acc[9]  = ffma2(z2, wA.y, acc[9]);
        acc[10]= ffma2(z2, wB.x, acc[10]); acc[11] = ffma2(z2, wB.y, acc[11]);
        acc[12]= ffma2(z3, wA.x, acc[12]); acc[13] = ffma2(z3, wB.x, acc[13]);
        acc[14]= ffma2(z3, wA.y, acc[14]); acc[15] = ffma2(z3, wB.y, acc[15]);
    }
}
__device__ __forceinline__ int accidx(int e, int op){
    if (e < 3) return e*4 + op;
    const int m[4] = {12,14,13,15};
    return m[op];
}
template<bool ACT, bool INPLACE>
__device__ __forceinline__ void gemm_store_smem(float* Zout, const float* bias,
                                                int eg, int og, ull* acc)
{
    float b[8];
#pragma unroll
    for (int q = 0; q < 8; q++) b[q] = bias[og*8+q];
    if (INPLACE) __syncthreads();
#pragma unroll
    for (int e = 0; e < 4; e++){
#pragma unroll
        for (int op = 0; op < 4; op++){
            ull A = acc[accidx(e,op)];
            float lo = f2lo(A) + b[2*op];
            float hi = f2hi(A) + b[2*op+1];
            if (ACT){ lo = lrelu(lo); hi = lrelu(hi); }
            Zout[(og*8+2*op)*128   + eg*4+e] = lo;
            Zout[(og*8+2*op+1)*128 + eg*4+e] = hi;
        }
    }
}
__device__ __forceinline__ void gemm_store_gu(float* gu, int r0,
                                              int eg, int og, ull* acc)
{
#pragma unroll
    for (int e = 0; e < 4; e++){
        int row = r0 + eg*4 + e;
        float4 v0 = make_float4(f2lo(acc[accidx(e,0)]), f2hi(acc[accidx(e,0)]),
                                f2lo(acc[accidx(e,1)]), f2hi(acc[accidx(e,1)]));
        float4 v1 = make_float4(f2lo(acc[accidx(e,2)]), f2hi(acc[accidx(e,2)]),
                                f2lo(acc[accidx(e,3)]), f2hi(acc[accidx(e,3)]));
        *reinterpret_cast<float4*>(gu + (size_t)row*64 + og*8)     = v0;
        *reinterpret_cast<float4*>(gu + (size_t)row*64 + og*8 + 4) = v1;
    }
}

// Final 64->10 layer, k-split by 2 (node): wsh padded to stride 12 -> 3 vec loads
__device__ __forceinline__ void layer10_node(const float* Zin, const float* wsh,
                                             float* part, int e, int kh)
{
    ull acc[5];
#pragma unroll
    for (int p = 0; p < 5; p++) acc[p] = 0ULL;
    const int k0 = kh*32;
#pragma unroll 4
    for (int kk = 0; kk < 32; kk++){
        int k = k0 + kk;
        ull z2 = splat2(Zin[k*128+e]);
        const ulonglong2* wp = reinterpret_cast<const ulonglong2*>(wsh + k*12);
        ulonglong2 wa = wp[0], wb = wp[1];
        ull wc = *reinterpret_cast<const ull*>(wsh + k*12 + 8);
        acc[0] = ffma2(z2, wa.x, acc[0]);
        acc[1] = ffma2(z2, wa.y, acc[1]);
        acc[2] = ffma2(z2, wb.x, acc[2]);
        acc[3] = ffma2(z2, wb.y, acc[3]);
        acc[4] = ffma2(z2, wc,   acc[4]);
    }
    float* pr = part + kh*1280 + e*10;
#pragma unroll
    for (int p = 0; p < 5; p++){ pr[p*2] = f2lo(acc[p]); pr[p*2+1] = f2hi(acc[p]); }
}

// Final 64->10 layer, full k (edge halves): one thread per edge row
__device__ __forceinline__ void layer10_full(const float* Zin, const float* wsh,
                                             float* part, int e)
{
    ull acc[5];
#pragma unroll
    for (int p = 0; p < 5; p++) acc[p] = 0ULL;
#pragma unroll 4
    for (int k = 0; k < 64; k++){
        ull z2 = splat2(Zin[k*128+e]);
        const ulonglong2* wp = reinterpret_cast<const ulonglong2*>(wsh + k*12);
        ulonglong2 wa = wp[0], wb = wp[1];
        ull wc = *reinterpret_cast<const ull*>(wsh + k*12 + 8);
        acc[0] = ffma2(z2, wa.x, acc[0]);
        acc[1] = ffma2(z2, wa.y, acc[1]);
        acc[2] = ffma2(z2, wb.x, acc[2]);
        acc[3] = ffma2(z2, wb.y, acc[3]);
        acc[4] = ffma2(z2, wc,   acc[4]);
    }
    float* pr = part + e*10;
#pragma unroll
    for (int p = 0; p < 5; p++){ pr[p*2] = f2lo(acc[p]); pr[p*2+1] = f2hi(acc[p]); }
}

// ---------------------------------------------------------------------------
// K2: per-node — u = hg@We0 (streamed to g_u), vp = MLP(hg) -> diag blocks.
// 128 nodes per block, 256 threads, grid 320, 3 blocks/SM (R9 proven + padded wsh)
// ---------------------------------------------------------------------------
#define K2_SMEM_FLOATS 15696
__global__ __launch_bounds__(256, 3) void node_kernel(
    const float* __restrict__ hg,
    const float* __restrict__ Wn0, const float* __restrict__ bn0,
    const float* __restrict__ Wn1, const float* __restrict__ bn1,
    const float* __restrict__ Wn2, const float* __restrict__ bn2,
    const float* __restrict__ We0,
    float* __restrict__ Xout)
{
    extern __shared__ float sm[];
    float* Z0   = sm;             // 8192
    float* Wsm  = sm + 8192;      // 4096
    float* wsh  = sm + 12288;     // 768 (64 x 12 padded)
    float* part = sm + 13056;     // 2560
    float* bsh  = sm + 15616;     // 64
    float* b2   = sm + 15680;     // 16

    const int tid = threadIdx.x;
    const int e  = tid & 127, kh = tid >> 7;
    const int eg = tid & 31,  og = tid >> 5;
    const int r0 = blockIdx.x * 128;
    ull acc[16];

    {
        const float4* row = reinterpret_cast<const float4*>(hg + (size_t)(r0+e)*64);
#pragma unroll
        for (int q = 0; q < 8; q++){
            float4 v = row[kh*8+q];
            int k = kh*32 + q*4;
            Z0[(k+0)*128+e]=v.x; Z0[(k+1)*128+e]=v.y; Z0[(k+2)*128+e]=v.z; Z0[(k+3)*128+e]=v.w;
        }
    }
    for (int i2 = tid; i2 < 4096; i2 += 256) Wsm[i2] = We0[i2];
    __syncthreads();
    gemm_main(Z0, Wsm, eg, og, acc);
    gemm_store_gu(g_u, r0, eg, og, acc);
    __syncthreads();
    for (int i2 = tid; i2 < 4096; i2 += 256) Wsm[i2] = Wn0[i2];
    for (int i2 = tid; i2 < 64; i2 += 256) bsh[i2] = bn0[i2];
    __syncthreads();
    gemm_main(Z0, Wsm, eg, og, acc);
    gemm_store_smem<true, true>(Z0, bsh, eg, og, acc);
    __syncthreads();
    for (int i2 = tid; i2 < 4096; i2 += 256) Wsm[i2] = Wn1[i2];
    for (int i2 = tid; i2 < 64; i2 += 256) bsh[i2] = bn1[i2];
    __syncthreads();
    gemm_main(Z0, Wsm, eg, og, acc);
    gemm_store_smem<true, true>(Z0, bsh, eg, og, acc);
    __syncthreads();
    for (int i2 = tid; i2 < 768; i2 += 256){
        int k = i2/12, o = i2 - k*12;
        wsh[i2] = (o < 10) ? Wn2[k*10+o] : 0.f;
    }
    if (tid < 10) b2[tid] = bn2[tid];
    __syncthreads();
    layer10_node(Z0, wsh, part, e, kh);
    __syncthreads();

#pragma unroll
    for (int p = 0; p < 2; p++){
        int idx = tid + p*256;
        int n = idx >> 2, a = idx & 3;
        int r = r0 + n, gg = r/40, i = r - gg*40;
        const float* p0 = part + n*10;
        const float* p1 = part + 1280 + n*10;
        int s0=c_smat[a*4], s1=c_smat[a*4+1], s2=c_smat[a*4+2], s3=c_smat[a*4+3];
        float4 v = make_float4(p0[s0]+p1[s0]+b2[s0], p0[s1]+p1[s1]+b2[s1],
                               p0[s2]+p1[s2]+b2[s2], p0[s3]+p1[s3]+b2[s3]);
        *reinterpret_cast<float4*>(Xout + (size_t)gg*X_PER_G + (i*4+a)*160 + i*4) = v;
    }
}

// ---------------------------------------------------------------------------
// K3: per-edge — one block per group (grid 1024, 256 threads), the block's two
// 128-thread halves process two 128-edge tiles concurrently (4 iterations
// cover tiles 0..7; tile 6 partial=12, tile 7 empty).
// GEMM thread tile r4c16: eg=tid&31 (4 edges), og=(tid>>5)&3 (16 outs),
// th=tid>>7 selects the tile. 256 MACs/wavefront (vs 171 r4c8).
// ---------------------------------------------------------------------------
// smem float offsets
#define E_UG     0       /* 40*68 = 2720 */
#define E_Z0A    2720    /* 8192 */
#define E_Z0B    10912   /* 8192 */
#define E_WSM    19104   /* 4096 */
#define E_WSH    23200   /* 768  */
#define E_PART   23968   /* 2560 (2 x 1280) */
#define E_B0     26528   /* 64 */
#define E_B1     26592   /* 64 */
#define E_B2     26656   /* 16 */
#define E_SI     26672   /* 256 ints (2 x 128) */
#define E_SJ     26928   /* 256 ints */
#define K3_SMEM_FLOATS 27184

__global__ __launch_bounds__(256, 2) void edge_kernel(
    const int* __restrict__ ud,   /* int32 pairs (i,j) */
    const float* __restrict__ be0,
    const float* __restrict__ We1, const float* __restrict__ be1,
    const float* __restrict__ We2, const float* __restrict__ be2,
    float* __restrict__ Xout)
{
    extern __shared__ float sm[];
    float* ug   = sm + E_UG;
    float* Wsm  = sm + E_WSM;
    float* wsh  = sm + E_WSH;
    float* part = sm + E_PART;
    float* b0   = sm + E_B0;
    float* b1   = sm + E_B1;
    float* b2   = sm + E_B2;
    int*   si   = (int*)(sm + E_SI);
    int*   sj   = (int*)(sm + E_SJ);

    const int tid = threadIdx.x;
    const int e   = tid & 127;          // edge row within half's tile
    const int th  = tid >> 7;           // which tile-half (0/1)
    const int eg  = tid & 31;           // 4 edges each
    const int og  = (tid >> 5) & 3;     // 16 outs each
    const int g   = blockIdx.x;

    float* Zt   = sm + (th ? E_Z0B : E_Z0A);
    float* myp  = part + th*1280;
    int*   msi  = si + th*128;
    int*   msj  = sj + th*128;

    // ---- setup (once per group) ----
    {   // group's u rows, stride 68 (float4-aligned)
        const float4* usrc = reinterpret_cast<const float4*>(g_u + (size_t)g*NN*64);
        for (int idx = tid; idx < NN*16; idx += 256){
            int n = idx >> 4, c4 = idx & 15;
            *reinterpret_cast<float4*>(ug + n*68 + c4*4) = usrc[idx];
        }
    }
    for (int i2 = tid; i2 < 4096; i2 += 256) Wsm[i2] = We1[i2];
    for (int i2 = tid; i2 < 64; i2 += 256){ b0[i2] = be0[i2]; b1[i2] = be1[i2]; }
    for (int i2 = tid; i2 < 768; i2 += 256){
        int k = i2/12, o = i2 - k*12;
        wsh[i2] = (o < 10) ? We2[k*10+o] : 0.f;
    }
    if (tid < 10) b2[tid] = be2[tid];

    float* Xg = Xout + (size_t)g*X_PER_G;
    ull acc[32];

    for (int it = 0; it < 4; it++){
        const int m0 = (it*2 + th) * 128;
        const int ecnt = max(0, min(128, M_EDGES - m0));

        __syncthreads();   // prev iter done with si/sj/Zt/part; setup visible (1st)
        if (tid - th*128 == e){  // all threads: each half's 128 threads load its tile
            int2 p = make_int2(0,0);
            if (e < ecnt) p = *reinterpret_cast<const int2*>(ud + 2*(m0+e));
            msi[e] = p.x; msj[e] = p.y;
        }
        __syncthreads();

        {   // z1 = lrelu(u_i+u_j+b0) -> Zt[k][e], one thread per edge, float4 reads
            const bool valid = e < ecnt;
            const int i = msi[e], j = msj[e];
            const float4* ui = reinterpret_cast<const float4*>(ug + i*68);
            const float4* uj = reinterpret_cast<const float4*>(ug + j*68);
            const float4* bb = reinterpret_cast<const float4*>(b0);
#pragma unroll 4
            for (int t = 0; t < 16; t++){
                float4 a = ui[t], c = uj[t], d = bb[t];
                int k = t*4;
                Zt[(k+0)*128+e] = valid ? lrelu(a.x+c.x+d.x) : 0.f;
                Zt[(k+1)*128+e] = valid ? lrelu(a.y+c.y+d.y) : 0.f;
                Zt[(k+2)*128+e] = valid ? lrelu(a.z+c.z+d.z) : 0.f;
                Zt[(k+3)*128+e] = valid ? lrelu(a.w+c.w+d.w) : 0.f;
            }
        }
        __syncthreads();

        // ---- GEMM r4c16: acc[e*8+op], e=0..3 edges, op=0..7 (f32x2 out pairs)
#pragma unroll
        for (int i2 = 0; i2 < 32; i2++) acc[i2] = 0ULL;
#pragma unroll 2
        for (int k = 0; k < 64; k++){
            float4 z = *reinterpret_cast<const float4*>(Zt + k*128 + eg*4);
            const ulonglong2* wp = reinterpret_cast<const ulonglong2*>(Wsm + k*64 + og*16);
            ulonglong2 wA = wp[0], wB = wp[1], wC = wp[2], wD = wp[3];
            ull z0 = splat2(z.x), z1 = splat2(z.y), z2 = splat2(z.z), z3 = splat2(z.w);
            acc[0]  = ffma2(z0, wA.x, acc[0]);  acc[1]  = ffma2(z0, wA.y, acc[1]);
            acc[2]  = ffma2(z0, wB.x, acc[2]);  acc[3]  = ffma2(z0, wB.y, acc[3]);
            acc[4]  = ffma2(z0, wC.x, acc[4]);  acc[5]  = ffma2(z0, wC.y, acc[5]);
            acc[6]  = ffma2(z0, wD.x, acc[6]);  acc[7]  = ffma2(z0, wD.y, acc[7]);
            acc[8]  = ffma2(z1, wA.x, acc[8]);  acc[9]  = ffma2(z1, wA.y, acc[9]);
            acc[10] = ffma2(z1, wB.x, acc[10]); acc[11] = ffma2(z1, wB.y, acc[11]);
            acc[12] = ffma2(z1, wC.x, acc[12]); acc[13] = ffma2(z1, wC.y, acc[13]);
            acc[14] = ffma2(z1, wD.x, acc[14]); acc[15] = ffma2(z1, wD.y, acc[15]);
            acc[16] = ffma2(z2, wA.x, acc[16]); acc[17] = ffma2(z2, wA.y, acc[17]);
            acc[18] = ffma2(z2, wB.x, acc[18]); acc[19] = ffma2(z2, wB.y, acc[19]);
            acc[20] = ffma2(z2, wC.x, acc[20]); acc[21] = ffma2(z2, wC.y, acc[21]);
            acc[22] = ffma2(z2, wD.x, acc[22]); acc[23] = ffma2(z2, wD.y, acc[23]);
            acc[24] = ffma2(z3, wA.x, acc[24]); acc[25] = ffma2(z3, wA.y, acc[25]);
            acc[26] = ffma2(z3, wB.x, acc[26]); acc[27] = ffma2(z3, wB.y, acc[27]);
            acc[28] = ffma2(z3, wC.x, acc[28]); acc[29] = ffma2(z3, wC.y, acc[29]);
            acc[30] = ffma2(z3, wD.x, acc[30]); acc[31] = ffma2(z3, wD.y, acc[31]);
        }
        __syncthreads();   // all reads of Zt done -> safe to overwrite in-place

        {   // epilogue: bias + lrelu, float4 stores over the 4 edges per out pair
#pragma unroll
            for (int op = 0; op < 8; op++){
                float blo = b1[og*16 + 2*op];
                float bhi = b1[og*16 + 2*op + 1];
                float4 lo = make_float4(lrelu(f2lo(acc[op])      + blo),
                                        lrelu(f2lo(acc[8+op])    + blo),
                                        lrelu(f2lo(acc[16+op])   + blo),
                                        lrelu(f2lo(acc[24+op])   + blo));
                float4 hi = make_float4(lrelu(f2hi(acc[op])      + bhi),
                                        lrelu(f2hi(acc[8+op])    + bhi),
                                        lrelu(f2hi(acc[16+op])   + bhi),
                                        lrelu(f2hi(acc[24+op])   + bhi));
                *reinterpret_cast<float4*>(Zt + (og*16+2*op)*128   + eg*4) = lo;
                *reinterpret_cast<float4*>(Zt + (og*16+2*op+1)*128 + eg*4) = hi;
            }
        }
        __syncthreads();

        layer10_full(Zt, wsh, myp, e);
        __syncthreads();

        {   // symmetric 4x4 block scatter: per half, 128 edges x 8 stores
            if (e < ecnt){
                int i = msi[e], j = msj[e];
                const float* p0 = myp + e*10;
#pragma unroll
                for (int a = 0; a < 4; a++){
                    int s0=c_smat[a*4], s1=c_smat[a*4+1], s2=c_smat[a*4+2], s3=c_smat[a*4+3];
                    float4 v = make_float4(p0[s0]+b2[s0], p0[s1]+b2[s1],
                                           p0[s2]+b2[s2], p0[s3]+b2[s3]);
                    *reinterpret_cast<float4*>(Xg + (i*4+a)*160 + j*4) = v;
                    *reinterpret_cast<float4*>(Xg + (j*4+a)*160 + i*4) = v;
                }
            }
        }
    }
}

// ---------------------------------------------------------------------------
extern "C" void kernel_launch(void* const* d_in, const int* in_sizes, int n_in,
                              void* d_out, int out_size)
{
    const float* x  = (const float*)d_in[0];
    const int*   ud = (const int*)d_in[2];   // int32 (JAX default x64 disabled)
    const float* Wg0 = (const float*)d_in[4];  const float* bg0 = (const float*)d_in[5];
    const float* Wg1 = (const float*)d_in[6];  const float* bg1 = (const float*)d_in[7];
    const float* Wg2 = (const float*)d_in[8];  const float* bg2 = (const float*)d_in[9];
    const float* Wn0 = (const float*)d_in[10]; const float* bn0 = (const float*)d_in[11];
    const float* Wn1 = (const float*)d_in[12]; const float* bn1 = (const float*)d_in[13];
    const float* Wn2 = (const float*)d_in[14]; const float* bn2 = (const float*)d_in[15];
    const float* We0 = (const float*)d_in[16]; const float* be0 = (const float*)d_in[17];
    const float* We1 = (const float*)d_in[18]; const float* be1 = (const float*)d_in[19];
    const float* We2 = (const float*)d_in[20]; const float* be2 = (const float*)d_in[21];

    float* hout;
    float* Xout;
    size_t osz = (size_t)out_size;
    if (osz >= (size_t)H_ELEMS + X_ELEMS){
        hout = (float*)d_out;
        Xout = (float*)d_out + H_ELEMS;
    } else if (osz >= X_ELEMS){
        cudaGetSymbolAddress((void**)&hout, g_h);
        Xout = (float*)d_out;
    } else {
        hout = (float*)d_out;
        cudaGetSymbolAddress((void**)&Xout, g_x);
    }

    cudaFuncSetAttribute(node_kernel, cudaFuncAttributeMaxDynamicSharedMemorySize,
                         K2_SMEM_FLOATS*4);
    cudaFuncSetAttribute(edge_kernel, cudaFuncAttributeMaxDynamicSharedMemorySize,
                         K3_SMEM_FLOATS*4);

    dummy_kernel<<<1, 32>>>();   // exactly one: edge_kernel lands in ncu slot #4
    gcn_kernel<<<NG, 128>>>(x, Wg0, bg0, Wg1, bg1, Wg2, bg2, hout);
    node_kernel<<<NODES/128, 256, K2_SMEM_FLOATS*4>>>(hout, Wn0, bn0, Wn1, bn1,
                                                      Wn2, bn2, We0, Xout);
    edge_kernel<<<NG, 256, K3_SMEM_FLOATS*4>>>(ud, be0, We1, be1,
                                               We2, be2, Xout);
}

// round 17
// speedup vs baseline: 1.1436x; 1.0083x over previous
#include <cuda_runtime.h>

#define NG 1024
#define NN 40
#define M_EDGES 780
#define NODES (NG*NN)          /* 40960 */
#define H_ELEMS (NODES*64)     /* 2621440 */
#define X_PER_G (160*160)      /* 25600 */
#define X_ELEMS ((size_t)NG*X_PER_G)

// scratch: u = hg @ We0 per node (10.5 MB, L2-resident)
__device__ float g_u[NODES * 64];
// fallback scratch if the harness's d_out does not cover h and/or X
__device__ float g_h[H_ELEMS];
__device__ float g_x[NG * X_PER_G];

__constant__ int c_smat[16] = {0,1,2,3, 1,4,5,6, 2,5,7,8, 3,6,8,9};

__device__ __forceinline__ float lrelu(float v){ return v > 0.f ? v : 0.1f*v; }

typedef unsigned long long ull;

// packed fp32x2 FMA (sm_10x): 2 MACs per instruction
__device__ __forceinline__ ull ffma2(ull a, ull b, ull c){
    ull d;
    asm("fma.rn.f32x2 %0, %1, %2, %3;" : "=l"(d) : "l"(a), "l"(b), "l"(c));
    return d;
}
__device__ __forceinline__ ull addf2(ull a, ull b){
    ull d;
    asm("add.rn.f32x2 %0, %1, %2;" : "=l"(d) : "l"(a), "l"(b));
    return d;
}
__device__ __forceinline__ ull splat2(float x){
    ull r;
    asm("mov.b64 %0, {%1, %1};" : "=l"(r) : "f"(x));
    return r;
}
__device__ __forceinline__ float f2lo(ull a){ return __uint_as_float((unsigned)(a & 0xffffffffULL)); }
__device__ __forceinline__ float f2hi(ull a){ return __uint_as_float((unsigned)(a >> 32)); }

// no-op kernel: ONE dummy puts edge_kernel in the ncu capture slot (#4)
__global__ void dummy_kernel(){}

// ---------------------------------------------------------------------------
// K1: GCN — complete graph => gcn(h)[j] = (colsum(t) - t[j])/39 + b, t = h@W
// ---------------------------------------------------------------------------
__global__ __launch_bounds__(128) void gcn_kernel(
    const float* __restrict__ x,
    const float* __restrict__ Wg0, const float* __restrict__ bg0,
    const float* __restrict__ Wg1, const float* __restrict__ bg1,
    const float* __restrict__ Wg2, const float* __restrict__ bg2,
    float* __restrict__ hout)
{
    __shared__ float sh[NN*64];
    __shared__ float st[NN*64];
    __shared__ float swt[64*36];
    __shared__ float ssum[64];
    const int g = blockIdx.x, tid = threadIdx.x;

    for (int idx = tid; idx < NN*64; idx += 128) sh[idx] = 0.f;
    __syncthreads();
    for (int idx = tid; idx < NN*6; idx += 128){
        int n = idx/6, c = idx - n*6;
        sh[n*64+c] = x[(g*NN+n)*16 + c];
    }
    __syncthreads();

    auto finish = [&](int outd, const float* b, bool act){
        for (int o = tid; o < outd; o += 128){
            float s = 0.f;
            for (int n = 0; n < NN; n++) s += st[n*64+o];
            ssum[o] = s;
        }
        __syncthreads();
        const float inv = 1.f/39.f;
        for (int idx = tid; idx < NN*outd; idx += 128){
            int n = idx/outd, o = idx - n*outd;
            float v = (ssum[o] - st[n*64+o])*inv + b[o];
            if (act) v = lrelu(v);
            sh[n*64+o] = v;
        }
        __syncthreads();
    };

    {
        for (int idx = tid; idx < 6*32; idx += 128) swt[idx] = Wg0[idx];
        __syncthreads();
        for (int idx = tid; idx < NN*32; idx += 128){
            int n = idx/32, o = idx & 31;
            float a = 0.f;
#pragma unroll
            for (int k = 0; k < 6; k++) a += sh[n*64+k]*swt[k*32+o];
            st[n*64+o] = a;
        }
        __syncthreads();
        finish(32, bg0, true);
    }

    auto layerV = [&](const float* W, const float* b, int outd, bool act){
        for (int idx = tid; idx < 32*outd; idx += 128){
            int k = idx / outd, o = idx - k*outd;
            swt[o*36 + k] = W[idx];
        }
        __syncthreads();
        for (int idx = tid; idx < NN*outd; idx += 128){
            int n = idx/outd, o = idx - n*outd;
            const float4* A = reinterpret_cast<const float4*>(sh + n*64);
            const float4* B = reinterpret_cast<const float4*>(swt + o*36);
            float ax=0.f, ay=0.f, az=0.f, aw=0.f;
#pragma unroll
            for (int q = 0; q < 8; q++){
                float4 a = A[q], w = B[q];
                ax += a.x*w.x; ay += a.y*w.y; az += a.z*w.z; aw += a.w*w.w;
            }
            st[n*64+o] = (ax+ay)+(az+aw);
        }
        __syncthreads();
        finish(outd, b, act);
    };
    layerV(Wg1, bg1, 32, true);
    layerV(Wg2, bg2, 64, false);

    float* hrow = hout + (size_t)g*NN*64;
    for (int idx = tid; idx < NN*64; idx += 128) hrow[idx] = sh[idx];
}

// ---------------------------------------------------------------------------
// SIMT 128x64x64 GEMM (r4c8, node kernel — R9 proven)
// ---------------------------------------------------------------------------
__device__ __forceinline__ void gemm_main(const float* Zin, const float* Wsm,
                                          int eg, int og, ull* acc)
{
#pragma unroll
    for (int i = 0; i < 16; i++) acc[i] = 0ULL;
#pragma unroll 4
    for (int k = 0; k < 64; k++){
        float4 z = *reinterpret_cast<const float4*>(Zin + k*128 + eg*4);
        ulonglong2 wA = *reinterpret_cast<const ulonglong2*>(Wsm + k*64 + og*8);
        ulonglong2 wB = *reinterpret_cast<const ulonglong2*>(Wsm + k*64 + og*8 + 4);
        ull z0 = splat2(z.x), z1 = splat2(z.y), z2 = splat2(z.z), z3 = splat2(z.w);
        acc[0] = ffma2(z0, wA.x, acc[0]);  acc[1]  = ffma2(z0, wA.y, acc[1]);
        acc[2] = ffma2(z0, wB.x, acc[2]);  acc[3]  = ffma2(z0, wB.y, acc[3]);
        acc[4] = ffma2(z1, wA.x, acc[4]);  acc[5]  = ffma2(z1, wA.y, acc[5]);
        acc[6] = ffma2(z1, wB.x, acc[6]);  acc[7]  = ffma2(z1, wB.y, acc[7]);
        acc[8] = ffma2(z2, wA.x, acc[8]);  acc[9]  = ffma2(z2, wA.y, acc[9]);
        acc[10]= ffma2(z2, wB.x, acc[10]); acc[11] = ffma2(z2, wB.y, acc[11]);
        acc[12]= ffma2(z3, wA.x, acc[12]); acc[13] = ffma2(z3, wB.x, acc[13]);
        acc[14]= ffma2(z3, wA.y, acc[14]); acc[15] = ffma2(z3, wB.y, acc[15]);
    }
}
__device__ __forceinline__ int accidx(int e, int op){
    if (e < 3) return e*4 + op;
    const int m[4] = {12,14,13,15};
    return m[op];
}
template<bool ACT, bool INPLACE>
__device__ __forceinline__ void gemm_store_smem(float* Zout, const float* bias,
                                                int eg, int og, ull* acc)
{
    float b[8];
#pragma unroll
    for (int q = 0; q < 8; q++) b[q] = bias[og*8+q];
    if (INPLACE) __syncthreads();
#pragma unroll
    for (int e = 0; e < 4; e++){
#pragma unroll
        for (int op = 0; op < 4; op++){
            ull A = acc[accidx(e,op)];
            float lo = f2lo(A) + b[2*op];
            float hi = f2hi(A) + b[2*op+1];
            if (ACT){ lo = lrelu(lo); hi = lrelu(hi); }
            Zout[(og*8+2*op)*128   + eg*4+e] = lo;
            Zout[(og*8+2*op+1)*128 + eg*4+e] = hi;
        }
    }
}
__device__ __forceinline__ void gemm_store_gu(float* gu, int r0,
                                              int eg, int og, ull* acc)
{
#pragma unroll
    for (int e = 0; e < 4; e++){
        int row = r0 + eg*4 + e;
        float4 v0 = make_float4(f2lo(acc[accidx(e,0)]), f2hi(acc[accidx(e,0)]),
                                f2lo(acc[accidx(e,1)]), f2hi(acc[accidx(e,1)]));
        float4 v1 = make_float4(f2lo(acc[accidx(e,2)]), f2hi(acc[accidx(e,2)]),
                                f2lo(acc[accidx(e,3)]), f2hi(acc[accidx(e,3)]));
        *reinterpret_cast<float4*>(gu + (size_t)row*64 + og*8)     = v0;
        *reinterpret_cast<float4*>(gu + (size_t)row*64 + og*8 + 4) = v1;
    }
}

// Final 64->10 layer, k-split by 2 (node): wsh padded to stride 12 -> 3 vec loads
__device__ __forceinline__ void layer10_node(const float* Zin, const float* wsh,
                                             float* part, int e, int kh)
{
    ull acc[5];
#pragma unroll
    for (int p = 0; p < 5; p++) acc[p] = 0ULL;
    const int k0 = kh*32;
#pragma unroll 4
    for (int kk = 0; kk < 32; kk++){
        int k = k0 + kk;
        ull z2 = splat2(Zin[k*128+e]);
        const ulonglong2* wp = reinterpret_cast<const ulonglong2*>(wsh + k*12);
        ulonglong2 wa = wp[0], wb = wp[1];
        ull wc = *reinterpret_cast<const ull*>(wsh + k*12 + 8);
        acc[0] = ffma2(z2, wa.x, acc[0]);
        acc[1] = ffma2(z2, wa.y, acc[1]);
        acc[2] = ffma2(z2, wb.x, acc[2]);
        acc[3] = ffma2(z2, wb.y, acc[3]);
        acc[4] = ffma2(z2, wc,   acc[4]);
    }
    float* pr = part + kh*1280 + e*10;
#pragma unroll
    for (int p = 0; p < 5; p++){ pr[p*2] = f2lo(acc[p]); pr[p*2+1] = f2hi(acc[p]); }
}

// ---------------------------------------------------------------------------
// K2: per-node — u = hg@We0 (streamed to g_u), vp = MLP(hg) -> diag blocks.
// (R16 proven config)
// ---------------------------------------------------------------------------
#define K2_SMEM_FLOATS 15696
__global__ __launch_bounds__(256, 3) void node_kernel(
    const float* __restrict__ hg,
    const float* __restrict__ Wn0, const float* __restrict__ bn0,
    const float* __restrict__ Wn1, const float* __restrict__ bn1,
    const float* __restrict__ Wn2, const float* __restrict__ bn2,
    const float* __restrict__ We0,
    float* __restrict__ Xout)
{
    extern __shared__ float sm[];
    float* Z0   = sm;             // 8192
    float* Wsm  = sm + 8192;      // 4096
    float* wsh  = sm + 12288;     // 768 (64 x 12 padded)
    float* part = sm + 13056;     // 2560
    float* bsh  = sm + 15616;     // 64
    float* b2   = sm + 15680;     // 16

    const int tid = threadIdx.x;
    const int e  = tid & 127, kh = tid >> 7;
    const int eg = tid & 31,  og = tid >> 5;
    const int r0 = blockIdx.x * 128;
    ull acc[16];

    {
        const float4* row = reinterpret_cast<const float4*>(hg + (size_t)(r0+e)*64);
#pragma unroll
        for (int q = 0; q < 8; q++){
            float4 v = row[kh*8+q];
            int k = kh*32 + q*4;
            Z0[(k+0)*128+e]=v.x; Z0[(k+1)*128+e]=v.y; Z0[(k+2)*128+e]=v.z; Z0[(k+3)*128+e]=v.w;
        }
    }
    for (int i2 = tid; i2 < 4096; i2 += 256) Wsm[i2] = We0[i2];
    __syncthreads();
    gemm_main(Z0, Wsm, eg, og, acc);
    gemm_store_gu(g_u, r0, eg, og, acc);
    __syncthreads();
    for (int i2 = tid; i2 < 4096; i2 += 256) Wsm[i2] = Wn0[i2];
    for (int i2 = tid; i2 < 64; i2 += 256) bsh[i2] = bn0[i2];
    __syncthreads();
    gemm_main(Z0, Wsm, eg, og, acc);
    gemm_store_smem<true, true>(Z0, bsh, eg, og, acc);
    __syncthreads();
    for (int i2 = tid; i2 < 4096; i2 += 256) Wsm[i2] = Wn1[i2];
    for (int i2 = tid; i2 < 64; i2 += 256) bsh[i2] = bn1[i2];
    __syncthreads();
    gemm_main(Z0, Wsm, eg, og, acc);
    gemm_store_smem<true, true>(Z0, bsh, eg, og, acc);
    __syncthreads();
    for (int i2 = tid; i2 < 768; i2 += 256){
        int k = i2/12, o = i2 - k*12;
        wsh[i2] = (o < 10) ? Wn2[k*10+o] : 0.f;
    }
    if (tid < 10) b2[tid] = bn2[tid];
    __syncthreads();
    layer10_node(Z0, wsh, part, e, kh);
    __syncthreads();

#pragma unroll
    for (int p = 0; p < 2; p++){
        int idx = tid + p*256;
        int n = idx >> 2, a = idx & 3;
        int r = r0 + n, gg = r/40, i = r - gg*40;
        const float* p0 = part + n*10;
        const float* p1 = part + 1280 + n*10;
        int s0=c_smat[a*4], s1=c_smat[a*4+1], s2=c_smat[a*4+2], s3=c_smat[a*4+3];
        float4 v = make_float4(p0[s0]+p1[s0]+b2[s0], p0[s1]+p1[s1]+b2[s1],
                               p0[s2]+p1[s2]+b2[s2], p0[s3]+p1[s3]+b2[s3]);
        *reinterpret_cast<float4*>(Xout + (size_t)gg*X_PER_G + (i*4+a)*160 + i*4) = v;
    }
}

// ---------------------------------------------------------------------------
// K3: per-edge — one block per group (grid 1024, 256 threads), two 128-edge
// tiles concurrently (th halves). Lane layout: og = t7&3 (16 outs), eg = t7>>2
// (4 edges). Interleaved We1 chunks -> 5 LDS wavefronts/warp/k in mainloop.
// layer10 fused into the epilogue in registers; og-partials reduced with
// butterfly shuffles (no Z2 smem roundtrip, no separate layer10 pass).
// ---------------------------------------------------------------------------
// smem float offsets
#define E_UG     0       /* 40*68 = 2720 */
#define E_Z0A    2720    /* 8192 */
#define E_Z0B    10912   /* 8192 */
#define E_WSM    19104   /* 4096, interleaved Wq[k][q][og][4] */
#define E_WSH4   23200   /* 4 copies x 194 = 776 (layer10 W, per-og, bank-disjoint) */
#define E_PART   23976   /* 2 x 1280 */
#define E_B0     26536   /* 64 */
#define E_B1     26600   /* 64 */
#define E_B2     26664   /* 16 */
#define E_SI     26680   /* 256 ints */
#define E_SJ     26936   /* 256 ints */
#define K3_SMEM_FLOATS 27192

__global__ __launch_bounds__(256, 2) void edge_kernel(
    const int* __restrict__ ud,   /* int32 pairs (i,j) */
    const float* __restrict__ be0,
    const float* __restrict__ We1, const float* __restrict__ be1,
    const float* __restrict__ We2, const float* __restrict__ be2,
    float* __restrict__ Xout)
{
    extern __shared__ float sm[];
    float* ug   = sm + E_UG;
    float* Wsm  = sm + E_WSM;
    float* wsh4 = sm + E_WSH4;
    float* part = sm + E_PART;
    float* b0   = sm + E_B0;
    float* b1   = sm + E_B1;
    float* b2   = sm + E_B2;
    int*   si   = (int*)(sm + E_SI);
    int*   sj   = (int*)(sm + E_SJ);

    const int tid = threadIdx.x;
    const int t7  = tid & 127;          // index within half
    const int th  = tid >> 7;           // tile-half (0/1)
    const int e   = t7;                 // z1-build / scatter edge row
    const int og  = t7 & 3;             // 16 outs each (low lane bits!)
    const int eg  = t7 >> 2;            // 4 edges each
    const int g   = blockIdx.x;

    float* Zt   = sm + (th ? E_Z0B : E_Z0A);
    float* myp  = part + th*1280;
    int*   msi  = si + th*128;
    int*   msj  = sj + th*128;

    // ---- setup (once per group) ----
    {   // group's u rows, stride 68 (float4-aligned)
        const float4* usrc = reinterpret_cast<const float4*>(g_u + (size_t)g*NN*64);
        for (int idx = tid; idx < NN*16; idx += 256){
            int n = idx >> 4, c4 = idx & 15;
            *reinterpret_cast<float4*>(ug + n*68 + c4*4) = usrc[idx];
        }
    }
    // We1 interleaved: Wsm[k*64 + q*16 + og*4 + j] = We1[k][og*16 + q*4 + j]
    for (int idx = tid; idx < 4096; idx += 256){
        int k = idx >> 6, o = idx & 63;
        int og_ = o >> 4, rem = o & 15, q = rem >> 2, j = rem & 3;
        Wsm[k*64 + q*16 + og_*4 + j] = We1[idx];
    }
    // We2 per-og copies, row stride 12, og stride 194 (bank-disjoint ull loads)
    for (int idx = tid; idx < 640; idx += 256){
        int kg = idx / 10, o = idx - kg*10;
        int og_ = kg >> 4, kk = kg & 15;
        wsh4[og_*194 + kk*12 + o] = We2[idx];
    }
    for (int i2 = tid; i2 < 64; i2 += 256){ b0[i2] = be0[i2]; b1[i2] = be1[i2]; }
    if (tid < 10) b2[tid] = be2[tid];

    float* Xg = Xout + (size_t)g*X_PER_G;
    ull acc[32];

    for (int it = 0; it < 4; it++){
        const int m0 = (it*2 + th) * 128;
        const int ecnt = max(0, min(128, M_EDGES - m0));

        __syncthreads();   // prev iter done with si/sj/Zt/part; setup visible (1st)
        {
            int2 p = make_int2(0,0);
            if (e < ecnt) p = *reinterpret_cast<const int2*>(ud + 2*(m0+e));
            msi[e] = p.x; msj[e] = p.y;
        }
        __syncthreads();

        {   // z1 = lrelu(u_i+u_j+b0) -> Zt[k][e], one thread per edge, float4 reads
            const bool valid = e < ecnt;
            const int i = msi[e], j = msj[e];
            const float4* ui = reinterpret_cast<const float4*>(ug + i*68);
            const float4* uj = reinterpret_cast<const float4*>(ug + j*68);
            const float4* bb = reinterpret_cast<const float4*>(b0);
#pragma unroll 4
            for (int t = 0; t < 16; t++){
                float4 a = ui[t], c = uj[t], d = bb[t];
                int k = t*4;
                Zt[(k+0)*128+e] = valid ? lrelu(a.x+c.x+d.x) : 0.f;
                Zt[(k+1)*128+e] = valid ? lrelu(a.y+c.y+d.y) : 0.f;
                Zt[(k+2)*128+e] = valid ? lrelu(a.z+c.z+d.z) : 0.f;
                Zt[(k+3)*128+e] = valid ? lrelu(a.w+c.w+d.w) : 0.f;
            }
        }
        __syncthreads();

        // ---- GEMM r4c16: acc[e*8+op], out pair for op = (outs og*16+2op, +1)
#pragma unroll
        for (int i2 = 0; i2 < 32; i2++) acc[i2] = 0ULL;
#pragma unroll 2
        for (int k = 0; k < 64; k++){
            float4 z = *reinterpret_cast<const float4*>(Zt + k*128 + eg*4);
            const float* wr = Wsm + k*64 + og*4;
            ulonglong2 w0 = *reinterpret_cast<const ulonglong2*>(wr);
            ulonglong2 w1 = *reinterpret_cast<const ulonglong2*>(wr + 16);
            ulonglong2 w2 = *reinterpret_cast<const ulonglong2*>(wr + 32);
            ulonglong2 w3 = *reinterpret_cast<const ulonglong2*>(wr + 48);
            ull z0 = splat2(z.x), z1 = splat2(z.y), z2 = splat2(z.z), z3 = splat2(z.w);
            acc[0]  = ffma2(z0, w0.x, acc[0]);  acc[1]  = ffma2(z0, w0.y, acc[1]);
            acc[2]  = ffma2(z0, w1.x, acc[2]);  acc[3]  = ffma2(z0, w1.y, acc[3]);
            acc[4]  = ffma2(z0, w2.x, acc[4]);  acc[5]  = ffma2(z0, w2.y, acc[5]);
            acc[6]  = ffma2(z0, w3.x, acc[6]);  acc[7]  = ffma2(z0, w3.y, acc[7]);
            acc[8]  = ffma2(z1, w0.x, acc[8]);  acc[9]  = ffma2(z1, w0.y, acc[9]);
            acc[10] = ffma2(z1, w1.x, acc[10]); acc[11] = ffma2(z1, w1.y, acc[11]);
            acc[12] = ffma2(z1, w2.x, acc[12]); acc[13] = ffma2(z1, w2.y, acc[13]);
            acc[14] = ffma2(z1, w3.x, acc[14]); acc[15] = ffma2(z1, w3.y, acc[15]);
            acc[16] = ffma2(z2, w0.x, acc[16]); acc[17] = ffma2(z2, w0.y, acc[17]);
            acc[18] = ffma2(z2, w1.x, acc[18]); acc[19] = ffma2(z2, w1.y, acc[19]);
            acc[20] = ffma2(z2, w2.x, acc[20]); acc[21] = ffma2(z2, w2.y, acc[21]);
            acc[22] = ffma2(z2, w3.x, acc[22]); acc[23] = ffma2(z2, w3.y, acc[23]);
            acc[24] = ffma2(z3, w0.x, acc[24]); acc[25] = ffma2(z3, w0.y, acc[25]);
            acc[26] = ffma2(z3, w1.x, acc[26]); acc[27] = ffma2(z3, w1.y, acc[27]);
            acc[28] = ffma2(z3, w2.x, acc[28]); acc[29] = ffma2(z3, w2.y, acc[29]);
            acc[30] = ffma2(z3, w3.x, acc[30]); acc[31] = ffma2(z3, w3.y, acc[31]);
        }

        // ---- fused epilogue: bias+lrelu in regs, partial layer10 over og's 16 k
        {
            ull p10[20];
#pragma unroll
            for (int c = 0; c < 20; c++) p10[c] = 0ULL;
            const float* wb = wsh4 + og*194;
#pragma unroll
            for (int op = 0; op < 8; op++){
                int out_lo = og*16 + 2*op;
                float blo = b1[out_lo], bhi = b1[out_lo+1];
                const ull* wl = reinterpret_cast<const ull*>(wb + (2*op)*12);
                const ull* wh = reinterpret_cast<const ull*>(wb + (2*op+1)*12);
                ull wl0=wl[0], wl1=wl[1], wl2=wl[2], wl3=wl[3], wl4=wl[4];
                ull wh0=wh[0], wh1=wh[1], wh2=wh[2], wh3=wh[3], wh4=wh[4];
#pragma unroll
                for (int ee = 0; ee < 4; ee++){
                    ull A = acc[ee*8+op];
                    ull zl = splat2(lrelu(f2lo(A) + blo));
                    ull zh = splat2(lrelu(f2hi(A) + bhi));
                    p10[ee*5+0] = ffma2(zl, wl0, p10[ee*5+0]);
                    p10[ee*5+0] = ffma2(zh, wh0, p10[ee*5+0]);
                    p10[ee*5+1] = ffma2(zl, wl1, p10[ee*5+1]);
                    p10[ee*5+1] = ffma2(zh, wh1, p10[ee*5+1]);
                    p10[ee*5+2] = ffma2(zl, wl2, p10[ee*5+2]);
                    p10[ee*5+2] = ffma2(zh, wh2, p10[ee*5+2]);
                    p10[ee*5+3] = ffma2(zl, wl3, p10[ee*5+3]);
                    p10[ee*5+3] = ffma2(zh, wh3, p10[ee*5+3]);
                    p10[ee*5+4] = ffma2(zl, wl4, p10[ee*5+4]);
                    p10[ee*5+4] = ffma2(zh, wh4, p10[ee*5+4]);
                }
            }
            // reduce across the 4 og lanes (same warp: lane^1 then lane^2)
#pragma unroll
            for (int c = 0; c < 20; c++){
                p10[c] = addf2(p10[c], __shfl_xor_sync(0xffffffffu, p10[c], 1));
                p10[c] = addf2(p10[c], __shfl_xor_sync(0xffffffffu, p10[c], 2));
            }
            if (og == 0){
#pragma unroll
                for (int ee = 0; ee < 4; ee++){
                    float* pr = myp + (eg*4+ee)*10;
#pragma unroll
                    for (int c = 0; c < 5; c++)
                        *reinterpret_cast<ull*>(pr + c*2) = p10[ee*5+c];
                }
            }
        }
        __syncthreads();

        {   // symmetric 4x4 block scatter: per half, 128 edges x 8 stores
            if (e < ecnt){
                int i = msi[e], j = msj[e];
                const float* p0 = myp + e*10;
#pragma unroll
                for (int a = 0; a < 4; a++){
                    int s0=c_smat[a*4], s1=c_smat[a*4+1], s2=c_smat[a*4+2], s3=c_smat[a*4+3];
                    float4 v = make_float4(p0[s0]+b2[s0], p0[s1]+b2[s1],
                                           p0[s2]+b2[s2], p0[s3]+b2[s3]);
                    *reinterpret_cast<float4*>(Xg + (i*4+a)*160 + j*4) = v;
                    *reinterpret_cast<float4*>(Xg + (j*4+a)*160 + i*4) = v;
                }
            }
        }
    }
}

// ---------------------------------------------------------------------------
extern "C" void kernel_launch(void* const* d_in, const int* in_sizes, int n_in,
                              void* d_out, int out_size)
{
    const float* x  = (const float*)d_in[0];
    const int*   ud = (const int*)d_in[2];   // int32 (JAX default x64 disabled)
    const float* Wg0 = (const float*)d_in[4];  const float* bg0 = (const float*)d_in[5];
    const float* Wg1 = (const float*)d_in[6];  const float* bg1 = (const float*)d_in[7];
    const float* Wg2 = (const float*)d_in[8];  const float* bg2 = (const float*)d_in[9];
    const float* Wn0 = (const float*)d_in[10]; const float* bn0 = (const float*)d_in[11];
    const float* Wn1 = (const float*)d_in[12]; const float* bn1 = (const float*)d_in[13];
    const float* Wn2 = (const float*)d_in[14]; const float* bn2 = (const float*)d_in[15];
    const float* We0 = (const float*)d_in[16]; const float* be0 = (const float*)d_in[17];
    const float* We1 = (const float*)d_in[18]; const float* be1 = (const float*)d_in[19];
    const float* We2 = (const float*)d_in[20]; const float* be2 = (const float*)d_in[21];

    float* hout;
    float* Xout;
    size_t osz = (size_t)out_size;
    if (osz >= (size_t)H_ELEMS + X_ELEMS){
        hout = (float*)d_out;
        Xout = (float*)d_out + H_ELEMS;
    } else if (osz >= X_ELEMS){
        cudaGetSymbolAddress((void**)&hout, g_h);
        Xout = (float*)d_out;
    } else {
        hout = (float*)d_out;
        cudaGetSymbolAddress((void**)&Xout, g_x);
    }

    cudaFuncSetAttribute(node_kernel, cudaFuncAttributeMaxDynamicSharedMemorySize,
                         K2_SMEM_FLOATS*4);
    cudaFuncSetAttribute(edge_kernel, cudaFuncAttributeMaxDynamicSharedMemorySize,
                         K3_SMEM_FLOATS*4);

    dummy_kernel<<<1, 32>>>();   // exactly one: edge_kernel lands in ncu slot #4
    gcn_kernel<<<NG, 128>>>(x, Wg0, bg0, Wg1, bg1, Wg2, bg2, hout);
    node_kernel<<<NODES/128, 256, K2_SMEM_FLOATS*4>>>(hout, Wn0, bn0, Wn1, bn1,
                                                      Wn2, bn2, We0, Xout);
    edge_kernel<<<NG, 256, K3_SMEM_FLOATS*4>>>(ud, be0, We1, be1,
                                               We2, be2, Xout);
}